// round 1
// baseline (speedup 1.0000x reference)
#include <cuda_runtime.h>
#include <cuda_bf16.h>
#include <math.h>

// ---------------- problem constants ----------------
#define BATCH 16
#define CH    3
#define HH    512
#define WW    512
#define HWPX  (HH*WW)          // 262144
#define ENC   256
#define MID   128
#define NUMK  262              // max(int(512*512*0.001),1)
#define BINS  4096
#define CANDMAX 4096

// ---------------- device scratch (statics allowed) ----------------
__device__ int   g_hist[BATCH][BINS];
__device__ int   g_cutbin[BATCH];
__device__ int   g_cand_cnt[BATCH];
__device__ float g_cand_val[BATCH][CANDMAX];
__device__ int   g_cand_idx[BATCH][CANDMAX];
__device__ float g_A[BATCH][3];
__device__ float g_invA[BATCH][3];
__device__ float g_params[BATCH];
__device__ float g_h1[BATCH*MID*256];        // post-leaky conv1 output (16x16 spatial)
__device__ float g_h1p[8][BATCH*MID*256];    // per-icg partials (deterministic reduce)
__device__ float g_W1t[ENC*9*MID];           // W1 transposed [ic][k][oc]
__device__ float g_dc2h[BATCH*HWPX];         // dc2 after horizontal min7
__device__ float g_dc2p[BATCH*HWPX];         // dc2 after full min-pool
__device__ unsigned int g_minkey, g_maxkey;

// ordered-uint encoding of float for exact atomic min/max
__device__ __forceinline__ unsigned int f2o(float f){
    unsigned int u = __float_as_uint(f);
    return (u & 0x80000000u) ? ~u : (u | 0x80000000u);
}
__device__ __forceinline__ float o2f(unsigned int o){
    return (o & 0x80000000u) ? __uint_as_float(o & 0x7FFFFFFFu)
                             : __uint_as_float(~o);
}

// ---------------- K0: init ----------------
__global__ void k_init(){
    int tid = threadIdx.x;
    int* h = &g_hist[0][0];
    for (int i = tid; i < BATCH*BINS; i += blockDim.x) h[i] = 0;
    if (tid < BATCH) g_cand_cnt[tid] = 0;
    if (tid == 0){ g_minkey = 0xFFFFFFFFu; g_maxkey = 0u; }
}

// ---------------- K1: transpose W1 -> [ic][k][oc] ----------------
__global__ void k_w1t(const float* __restrict__ W1){
    int e = blockIdx.x*blockDim.x + threadIdx.x;
    if (e >= ENC*9*MID) return;
    int oc = e & 127;
    int r  = e >> 7;          // ic*9 + k
    int k  = r % 9;
    int ic = r / 9;
    g_W1t[e] = W1[oc*(ENC*9) + ic*9 + k];
}

// ---------------- K2: dark-channel histogram ----------------
__global__ void k_hist(const float* __restrict__ x){
    __shared__ int sh[BINS];
    int tid = threadIdx.x;
    int b = blockIdx.y, chunk = blockIdx.x;
    for (int i = tid; i < BINS; i += 256) sh[i] = 0;
    __syncthreads();
    const float* xb = x + (size_t)b*3*HWPX;
    for (int it = 0; it < 16; it++){
        int i4 = chunk*4096 + it*256 + tid;     // float4 index
        float4 a0 = *(const float4*)(xb + 0*HWPX + i4*4);
        float4 a1 = *(const float4*)(xb + 1*HWPX + i4*4);
        float4 a2 = *(const float4*)(xb + 2*HWPX + i4*4);
        float d0 = fminf(fminf(a0.x,a1.x),a2.x);
        float d1 = fminf(fminf(a0.y,a1.y),a2.y);
        float d2 = fminf(fminf(a0.z,a1.z),a2.z);
        float d3 = fminf(fminf(a0.w,a1.w),a2.w);
        atomicAdd(&sh[min(BINS-1,(int)(d0*(float)BINS))],1);
        atomicAdd(&sh[min(BINS-1,(int)(d1*(float)BINS))],1);
        atomicAdd(&sh[min(BINS-1,(int)(d2*(float)BINS))],1);
        atomicAdd(&sh[min(BINS-1,(int)(d3*(float)BINS))],1);
    }
    __syncthreads();
    for (int i = tid; i < BINS; i += 256)
        if (sh[i]) atomicAdd(&g_hist[b][i], sh[i]);
}

// ---------------- K3: cutoff bin scan ----------------
__global__ void k_cutoff(){
    int b = blockIdx.x;
    if (threadIdx.x == 0){
        int cum = 0, cb = 0;
        for (int bin = BINS-1; bin >= 0; bin--){
            cum += g_hist[b][bin];
            if (cum >= NUMK){ cb = bin; break; }
        }
        g_cutbin[b] = cb;
    }
}

// ---------------- K4: gather candidates (>= cutoff bin) ----------------
__global__ void k_gather(const float* __restrict__ x){
    int tid = threadIdx.x;
    int b = blockIdx.y, chunk = blockIdx.x;
    int cb = g_cutbin[b];
    const float* xb = x + (size_t)b*3*HWPX;
    for (int it = 0; it < 16; it++){
        int i4 = chunk*4096 + it*256 + tid;
        float4 a0 = *(const float4*)(xb + 0*HWPX + i4*4);
        float4 a1 = *(const float4*)(xb + 1*HWPX + i4*4);
        float4 a2 = *(const float4*)(xb + 2*HWPX + i4*4);
        float d[4];
        d[0] = fminf(fminf(a0.x,a1.x),a2.x);
        d[1] = fminf(fminf(a0.y,a1.y),a2.y);
        d[2] = fminf(fminf(a0.z,a1.z),a2.z);
        d[3] = fminf(fminf(a0.w,a1.w),a2.w);
        #pragma unroll
        for (int j = 0; j < 4; j++){
            int bin = min(BINS-1,(int)(d[j]*(float)BINS));
            if (bin >= cb){
                int pos = atomicAdd(&g_cand_cnt[b], 1);
                if (pos < CANDMAX){
                    g_cand_val[b][pos] = d[j];
                    g_cand_idx[b][pos] = i4*4 + j;
                }
            }
        }
    }
}

// ---------------- K5: exact top-NUMK selection + A ----------------
__global__ void k_A(const float* __restrict__ x){
    __shared__ int sel[NUMK];
    int b = blockIdx.x, tid = threadIdx.x;
    int n = g_cand_cnt[b]; if (n > CANDMAX) n = CANDMAX;
    for (int i = tid; i < n; i += 256){
        float v = g_cand_val[b][i];
        int   id = g_cand_idx[b][i];
        int rank = 0;
        for (int j = 0; j < n; j++){
            float vj = g_cand_val[b][j];
            int   ij = g_cand_idx[b][j];
            rank += (vj > v) || (vj == v && ij < id);
        }
        if (rank < NUMK) sel[rank] = id;
    }
    __syncthreads();
    if (tid < 3){
        const float* xc = x + (size_t)b*3*HWPX + (size_t)tid*HWPX;
        float s = 0.f;
        for (int r = 0; r < NUMK; r++) s += xc[sel[r]];
        float A = s * (1.0f/(float)NUMK);
        g_A[b][tid] = A;
        g_invA[b][tid] = 1.0f / A;
    }
}

// ---------------- K6: conv1 (strided 3x3, 256->128ch), partial sums ----------------
// grid (icg=8, ocg=2, b=16); block 256; each block: 32 ic slice, 64 oc, full 16x16
__global__ void k_conv1(const float* __restrict__ latent){
    extern __shared__ float sh[];
    float* shIn = sh;                  // [16][34][34]
    float* shW  = sh + 16*34*34;       // [16][9][64]
    int icg = blockIdx.x, ocg = blockIdx.y, b = blockIdx.z;
    int tid = threadIdx.x;
    int og = tid >> 4;                 // 0..15 -> 4 oc each
    int sg = tid & 15;                 // 4x4 spatial subtile
    int sy0 = (sg >> 2) << 2;
    int sx0 = (sg & 3) << 2;

    float acc[4][16];
    #pragma unroll
    for (int a = 0; a < 4; a++)
        #pragma unroll
        for (int s = 0; s < 16; s++) acc[a][s] = 0.f;

    const float* lat = latent + (size_t)b*ENC*1024;

    for (int chunk = 0; chunk < 2; chunk++){
        int icbase = icg*32 + chunk*16;
        __syncthreads();
        // load input tile with zero pad (34x34)
        for (int e = tid; e < 16*1156; e += 256){
            int ic = e / 1156; int r = e - ic*1156;
            int yy = r / 34;   int xx = r - yy*34;
            int y = yy - 1, xpos = xx - 1;
            float v = 0.f;
            if ((unsigned)y < 32u && (unsigned)xpos < 32u)
                v = lat[(icbase+ic)*1024 + y*32 + xpos];
            shIn[e] = v;
        }
        // load transposed weights
        for (int e = tid; e < 16*9*64; e += 256){
            int icl = e / 576; int r = e - icl*576;
            int k = r >> 6; int ocl = r & 63;
            shW[e] = g_W1t[((icbase+icl)*9 + k)*MID + ocg*64 + ocl];
        }
        __syncthreads();
        for (int icl = 0; icl < 16; icl++){
            const float* wp = shW + icl*576 + og*4;
            const float* ip = shIn + icl*1156;
            #pragma unroll
            for (int ky = 0; ky < 3; ky++){
                #pragma unroll
                for (int kx = 0; kx < 3; kx++){
                    float4 wv = *(const float4*)(wp + (ky*3+kx)*64);
                    #pragma unroll
                    for (int i = 0; i < 4; i++){
                        const float* rp = ip + (2*(sy0+i)+ky)*34 + 2*sx0 + kx;
                        #pragma unroll
                        for (int j = 0; j < 4; j++){
                            float xin = rp[2*j];
                            int sp = i*4 + j;
                            acc[0][sp] += wv.x * xin;
                            acc[1][sp] += wv.y * xin;
                            acc[2][sp] += wv.z * xin;
                            acc[3][sp] += wv.w * xin;
                        }
                    }
                }
            }
        }
    }
    // store partials
    #pragma unroll
    for (int a = 0; a < 4; a++){
        int oc = ocg*64 + og*4 + a;
        float* dst = &g_h1p[icg][((size_t)(b*MID + oc)) << 8];
        #pragma unroll
        for (int i = 0; i < 4; i++)
            #pragma unroll
            for (int j = 0; j < 4; j++)
                dst[((sy0+i)<<4) + (sx0+j)] = acc[a][i*4+j];
    }
}

// ---------------- K7: reduce partials + bias + leaky ----------------
__global__ void k_reduce(const float* __restrict__ b1){
    int idx = blockIdx.x*blockDim.x + threadIdx.x;
    int stride = gridDim.x*blockDim.x;
    for (int i = idx; i < BATCH*MID*256; i += stride){
        int oc = (i >> 8) & (MID-1);
        float v = b1[oc];
        #pragma unroll
        for (int g = 0; g < 8; g++) v += g_h1p[g][i];
        v = (v >= 0.f) ? v : 0.02f*v;
        g_h1[i] = v;
    }
}

// ---------------- K8: conv2 + mean + conv3 + tanh -> params ----------------
__global__ void k_params(const float* __restrict__ W2, const float* __restrict__ b2,
                         const float* __restrict__ W3, const float* __restrict__ b3){
    __shared__ float red[256];
    __shared__ float red2[64];
    int b = blockIdx.x, tid = threadIdx.x;
    int out = tid >> 2;        // 0..63
    int q = tid & 3;           // ic quarter
    int oy = out >> 3, ox = out & 7;
    const float* h1 = &g_h1[(size_t)b*MID*256];
    float s = 0.f;
    for (int ic = q*32; ic < q*32 + 32; ic++){
        #pragma unroll
        for (int ky = 0; ky < 3; ky++){
            int y = 2*oy + ky - 1;
            if ((unsigned)y >= 16u) continue;
            #pragma unroll
            for (int kx = 0; kx < 3; kx++){
                int xx = 2*ox + kx - 1;
                if ((unsigned)xx >= 16u) continue;
                s += W2[ic*9 + ky*3 + kx] * h1[(ic<<8) + (y<<4) + xx];
            }
        }
    }
    red[tid] = s;
    __syncthreads();
    if (tid < 64) red2[tid] = red[tid*4] + red[tid*4+1] + red[tid*4+2] + red[tid*4+3];
    __syncthreads();
    if (tid == 0){
        float msum = 0.f;
        for (int o = 0; o < 64; o++) msum += red2[o];
        float h = msum * (1.0f/64.0f) + b2[0];
        float v = h * W3[0] + b3[0];
        g_params[b] = 0.5f*tanhf(v) + 0.5f;
    }
}

// ---------------- K9: dc2 + horizontal min7 ----------------
__global__ void k_dc2h(const float* __restrict__ x){
    __shared__ float dc[WW];
    int b = blockIdx.y, y = blockIdx.x;
    int tid = threadIdx.x;           // 128 threads, 4 cols each
    const float* xb = x + (size_t)b*3*HWPX + (size_t)y*WW;
    float ia0 = g_invA[b][0], ia1 = g_invA[b][1], ia2 = g_invA[b][2];
    float4 a0 = *(const float4*)(xb + 0*HWPX + tid*4);
    float4 a1 = *(const float4*)(xb + 1*HWPX + tid*4);
    float4 a2 = *(const float4*)(xb + 2*HWPX + tid*4);
    dc[tid*4+0] = fminf(fminf(a0.x*ia0, a1.x*ia1), a2.x*ia2);
    dc[tid*4+1] = fminf(fminf(a0.y*ia0, a1.y*ia1), a2.y*ia2);
    dc[tid*4+2] = fminf(fminf(a0.z*ia0, a1.z*ia1), a2.z*ia2);
    dc[tid*4+3] = fminf(fminf(a0.w*ia0, a1.w*ia1), a2.w*ia2);
    __syncthreads();
    float o[4];
    #pragma unroll
    for (int j = 0; j < 4; j++){
        int col = tid*4 + j;
        float m = dc[col];
        #pragma unroll
        for (int dx = -3; dx <= 3; dx++){
            int cc = col + dx;
            if ((unsigned)cc < (unsigned)WW) m = fminf(m, dc[cc]);
        }
        o[j] = m;
    }
    *(float4*)(&g_dc2h[(size_t)b*HWPX + (size_t)y*WW + tid*4]) = make_float4(o[0],o[1],o[2],o[3]);
}

// ---------------- K10: vertical min7 ----------------
__global__ void k_dc2v(){
    int colblk = blockIdx.x;           // 2
    int rowseg = blockIdx.y;           // 4 segments of 128 rows
    int b = blockIdx.z;
    int col = colblk*256 + threadIdx.x;
    int y0 = rowseg*128;
    const float* src = &g_dc2h[(size_t)b*HWPX];
    float* dst = &g_dc2p[(size_t)b*HWPX];
    for (int y = y0; y < y0 + 128; y++){
        float m = 3.4e38f;
        #pragma unroll
        for (int dy = -3; dy <= 3; dy++){
            int yy = y + dy;
            if ((unsigned)yy < (unsigned)HH) m = fminf(m, src[yy*WW + col]);
        }
        dst[y*WW + col] = m;
    }
}

// ---------------- K11: global min/max of out (recompute) ----------------
__global__ void k_minmax(const float* __restrict__ x){
    __shared__ float smn[256], smx[256];
    int tid = threadIdx.x;
    int idx4 = blockIdx.x*256 + tid;        // 0..1048575
    int b = idx4 >> 16;
    int i4 = idx4 & 65535;
    float p = g_params[b];
    float4 dcv = *(const float4*)(&g_dc2p[(size_t)b*HWPX + i4*4]);
    float t0 = fmaxf(1.f - p*dcv.x, 0.01f);
    float t1 = fmaxf(1.f - p*dcv.y, 0.01f);
    float t2 = fmaxf(1.f - p*dcv.z, 0.01f);
    float t3 = fmaxf(1.f - p*dcv.w, 0.01f);
    float mn = 3.4e38f, mx = -3.4e38f;
    #pragma unroll
    for (int c = 0; c < 3; c++){
        float A = g_A[b][c];
        float4 xv = *(const float4*)(x + (size_t)b*3*HWPX + (size_t)c*HWPX + i4*4);
        float o0 = (xv.x - A)/t0 + A;
        float o1 = (xv.y - A)/t1 + A;
        float o2 = (xv.z - A)/t2 + A;
        float o3 = (xv.w - A)/t3 + A;
        mn = fminf(mn, fminf(fminf(o0,o1), fminf(o2,o3)));
        mx = fmaxf(mx, fmaxf(fmaxf(o0,o1), fmaxf(o2,o3)));
    }
    smn[tid] = mn; smx[tid] = mx;
    __syncthreads();
    for (int s = 128; s > 0; s >>= 1){
        if (tid < s){
            smn[tid] = fminf(smn[tid], smn[tid+s]);
            smx[tid] = fmaxf(smx[tid], smx[tid+s]);
        }
        __syncthreads();
    }
    if (tid == 0){
        atomicMin(&g_minkey, f2o(smn[0]));
        atomicMax(&g_maxkey, f2o(smx[0]));
    }
}

// ---------------- K12: final normalize + write ----------------
__global__ void k_final(const float* __restrict__ x, float* __restrict__ out){
    int tid = threadIdx.x;
    int idx4 = blockIdx.x*256 + tid;
    int b = idx4 >> 16;
    int i4 = idx4 & 65535;
    float p = g_params[b];
    float mn = o2f(g_minkey);
    float mx = o2f(g_maxkey);
    float scale = 1.0f / (mx - mn);
    float4 dcv = *(const float4*)(&g_dc2p[(size_t)b*HWPX + i4*4]);
    float t0 = fmaxf(1.f - p*dcv.x, 0.01f);
    float t1 = fmaxf(1.f - p*dcv.y, 0.01f);
    float t2 = fmaxf(1.f - p*dcv.z, 0.01f);
    float t3 = fmaxf(1.f - p*dcv.w, 0.01f);
    #pragma unroll
    for (int c = 0; c < 3; c++){
        float A = g_A[b][c];
        size_t off = (size_t)b*3*HWPX + (size_t)c*HWPX + i4*4;
        float4 xv = *(const float4*)(x + off);
        float4 ov;
        ov.x = ((xv.x - A)/t0 + A - mn)*scale;
        ov.y = ((xv.y - A)/t1 + A - mn)*scale;
        ov.z = ((xv.z - A)/t2 + A - mn)*scale;
        ov.w = ((xv.w - A)/t3 + A - mn)*scale;
        *(float4*)(out + off) = ov;
    }
}

// ---------------- launch ----------------
extern "C" void kernel_launch(void* const* d_in, const int* in_sizes, int n_in,
                              void* d_out, int out_size){
    const float* x      = (const float*)d_in[0];
    const float* latent = (const float*)d_in[1];
    const float* W1     = (const float*)d_in[2];
    const float* b1     = (const float*)d_in[3];
    const float* W2     = (const float*)d_in[4];
    const float* b2     = (const float*)d_in[5];
    const float* W3     = (const float*)d_in[6];
    const float* b3     = (const float*)d_in[7];
    float* out = (float*)d_out;

    int convShmem = (16*34*34 + 16*9*64) * 4;   // 110848 B
    cudaFuncSetAttribute(k_conv1, cudaFuncAttributeMaxDynamicSharedMemorySize, convShmem);

    k_init<<<1, 256>>>();
    k_w1t<<<(ENC*9*MID + 255)/256, 256>>>(W1);
    k_hist<<<dim3(16, BATCH), 256>>>(x);
    k_cutoff<<<BATCH, 32>>>();
    k_gather<<<dim3(16, BATCH), 256>>>(x);
    k_A<<<BATCH, 256>>>(x);
    k_conv1<<<dim3(8, 2, BATCH), 256, convShmem>>>(latent);
    k_reduce<<<512, 256>>>(b1);
    k_params<<<BATCH, 256>>>(W2, b2, W3, b3);
    k_dc2h<<<dim3(HH, BATCH), 128>>>(x);
    k_dc2v<<<dim3(2, 4, BATCH), 256>>>();
    k_minmax<<<4096, 256>>>(x);
    k_final<<<4096, 256>>>(x, out);
}